// round 14
// baseline (speedup 1.0000x reference)
#include <cuda_runtime.h>

// ---------------------------------------------------------------------------
// Quantized LSTM — R6 structure verbatim (single synchronous speculative grid
// barrier per step: red.max cells + counter, tiered fixups), plus exactly:
//  1) fast activations (__expf/__fdividef; monotone -> verify stays exact)
//  2) speculative h written in phase C with predicted kh (cell 7 verifies;
//     kh-only miss = local rewrite) -> hit path does nothing post-barrier
//  3) fire-and-forget counter: red.release.add + ld.acquire poll
// ---------------------------------------------------------------------------

#define GB       128
#define BPB      8
#define NT       640
#define T_STEPS  1024
#define NI       10
#define NH       20
#define NG       80
#define CSTRIDE  64              // 256B between cells
#define NCELL    16              // 0-7 main, 8 kh-fix, 9-10 full-fix, 11 retry

__device__ __align__(128) unsigned g_ctr0[32];
__device__ unsigned g_cells[T_STEPS * NCELL * CSTRIDE];

__global__ void qlstm_init() {
    int i = blockIdx.x * blockDim.x + threadIdx.x;   // 16384 = T_STEPS*NCELL
    if (i == 0) g_ctr0[0] = 0u;
    if (i < T_STEPS * NCELL) g_cells[i * CSTRIDE] = 0u;
}

__device__ __forceinline__ unsigned mapf(float f) {
    unsigned u = __float_as_uint(f);
    return (u & 0x80000000u) ? ~u : (u | 0x80000000u);
}
__device__ __forceinline__ float unmapf(unsigned u) {
    return __uint_as_float((u & 0x80000000u) ? (u & 0x7FFFFFFFu) : ~u);
}
__device__ __forceinline__ int po2k(float m) {
    m = fmaxf(m, 1e-8f);
    int e; float f = frexpf(m, &e);
    return (f == 0.5f) ? (e - 1) : e;
}
__device__ __forceinline__ float sc(int k)    { return __uint_as_float((unsigned)(k + 120) << 23); }
__device__ __forceinline__ float scinv(int k) { return __uint_as_float((unsigned)(134 - k) << 23); }
__device__ __forceinline__ float fq1(float x, float s, float inv) {
    float q = rintf(x * inv);
    q = fminf(fmaxf(q, -128.0f), 127.0f);
    return q * s;
}
// fast activations: MUFU-based, monotone, ~1e-6 abs error (absorbed by int8 grid)
__device__ __forceinline__ float sigm(float x) {
    return __fdividef(1.0f, 1.0f + __expf(-x));
}
__device__ __forceinline__ float tanh_fast(float x) {
    return fmaf(-2.0f, __fdividef(1.0f, 1.0f + __expf(2.0f * x)), 1.0f);
}
__device__ __forceinline__ unsigned warp_max_u(unsigned v) {
#pragma unroll
    for (int o = 16; o; o >>= 1) v = max(v, __shfl_xor_sync(0xffffffffu, v, o));
    return v;
}
__device__ __forceinline__ void red_max_rlx(unsigned* p, unsigned v) {
    asm volatile("red.relaxed.gpu.max.u32 [%0],%1;" :: "l"(p), "r"(v) : "memory");
}
__device__ __forceinline__ void red_add_rel(unsigned* p, unsigned v) {
    asm volatile("red.release.gpu.add.u32 [%0],%1;" :: "l"(p), "r"(v) : "memory");
}
__device__ __forceinline__ unsigned ld_acq(const unsigned* p) {
    unsigned v; asm volatile("ld.acquire.gpu.u32 %0,[%1];" : "=r"(v) : "l"(p) : "memory"); return v;
}
__device__ __forceinline__ unsigned ld_rlx(const unsigned* p) {
    unsigned v; asm volatile("ld.relaxed.gpu.u32 %0,[%1];" : "=r"(v) : "l"(p) : "memory"); return v;
}

// fallback grid round (rare path)
__device__ __forceinline__ unsigned grid_bar(unsigned* cell0, unsigned myv, int nc,
                                             unsigned tgt, int lane) {
    if (lane < nc) red_max_rlx(cell0 + lane * CSTRIDE, myv);
    __syncwarp();
    if (lane == 0) red_add_rel(&g_ctr0[0], 1u);
    if (lane < nc) { while (ld_acq(&g_ctr0[0]) < tgt) { } }
    __syncwarp();
    return (lane < nc) ? ld_rlx(cell0 + lane * CSTRIDE) : 0u;
}

__global__ void __launch_bounds__(NT, 1) qlstm_main(
    const float* __restrict__ x,
    const float* __restrict__ Wih,
    const float* __restrict__ Whh,
    float* __restrict__ out)
{
    __shared__ __align__(16) float sh_h[BPB * NH];
    __shared__ __align__(16) float sh_x[BPB * NI];
    __shared__ float               sh_act[NG * BPB];
    __shared__ unsigned            sh_red[12];
    __shared__ int                 sh_k[8];    // true: 0:k1 1-4:ka 5:k3 6:kh 7:code
    __shared__ int                 sh_kp[8];   // predictions

    const int tid  = threadIdx.x;
    const int bid  = blockIdx.x;
    const int g    = tid / BPB;
    const int b    = tid % BPB;
    const int gr   = tid / 160;          // warp-uniform gate group
    const int lane = tid & 31;
    const int wid  = tid >> 5;

    if (tid < 12) sh_red[tid] = 0u;
    if (tid < 8)  { sh_kp[tid] = 99; sh_k[tid] = 0; }   // garbage -> full miss at t=0
    if (tid < BPB * NH) sh_h[tid] = 0.0f;
    __syncthreads();

    // ---- weight scale (block-local, once) ----
    {
        float wm = 0.0f;
        for (int k = tid; k < NG * NI; k += NT) wm = fmaxf(wm, fabsf(Wih[k]));
        for (int k = tid; k < NG * NH; k += NT) wm = fmaxf(wm, fabsf(Whh[k]));
        unsigned u = warp_max_u(__float_as_uint(wm));
        if (lane == 0) atomicMax(&sh_red[11], u);
        __syncthreads();
    }
    int kw = po2k(__uint_as_float(sh_red[11]));
    float ws = sc(kw), wsi = scinv(kw);
    __syncthreads();
    if (tid == 0) sh_red[11] = 0u;
    __syncthreads();

    float wi[NI], wh[NH];
#pragma unroll
    for (int i2 = 0; i2 < NI; i2++) wi[i2] = fq1(Wih[g * NI + i2], ws, wsi);
#pragma unroll
    for (int j2 = 0; j2 < NH; j2++) wh[j2] = fq1(Whh[g * NH + j2], ws, wsi);

    float    c = 0.0f, c_prev = 0.0f;
    float    tc = 0.0f, oq = 0.0f, hp = 0.0f;
    unsigned nbar = 0;

    const int sq  = tid - 560;           // warps 17-19 stage x
    const int sxb = (sq >= 0) ? sq / NI : 0;
    const int sxi = (sq >= 0) ? sq % NI : 0;
    float xr = 0.0f;
    if (sq >= 0) {
        sh_x[sq] = x[((size_t)(bid * BPB + sxb) * T_STEPS + 0) * NI + sxi];
        xr       = x[((size_t)(bid * BPB + sxb) * T_STEPS + 1) * NI + sxi];
    }
    __syncthreads();

    for (int t = 0; t < T_STEPS; ++t) {
        const int k1p = sh_kp[0], kap = sh_kp[1 + gr], k3p = sh_kp[5], khp = sh_kp[6];
        unsigned* cb = &g_cells[(size_t)t * NCELL * CSTRIDE];

        // ===== phase B: pre + gate group extrema + speculative activations =====
        float p0 = 0.0f, p1 = 0.0f;
        {
            const float2* px = reinterpret_cast<const float2*>(&sh_x[b * NI]);
            const float2* ph = reinterpret_cast<const float2*>(&sh_h[b * NH]);
#pragma unroll
            for (int j = 0; j < NI / 2; j++) {
                float2 v = px[j];
                p0 = fmaf(v.x, wi[2 * j], p0); p1 = fmaf(v.y, wi[2 * j + 1], p1);
            }
#pragma unroll
            for (int j = 0; j < NH / 2; j++) {
                float2 v = ph[j];
                p0 = fmaf(v.x, wh[2 * j], p0); p1 = fmaf(v.y, wh[2 * j + 1], p1);
            }
        }
        float pre = p0 + p1;
        unsigned kp = warp_max_u(mapf(pre));
        unsigned kn = warp_max_u(mapf(-pre));
        if (lane == 0) { atomicMax(&sh_red[gr], kp); atomicMax(&sh_red[4 + gr], kn); }
        {
            float gq  = fq1(pre, sc(k1p), scinv(k1p));
            float act = (gr == 2) ? tanh_fast(gq) : sigm(gq);
            sh_act[tid] = fq1(act, sc(kap), scinv(kap));
        }
        __syncthreads();                                        // S1
        if (sq >= 0 && t + 1 < T_STEPS) sh_x[sq] = xr;

        // ===== phase C (tid<160): c, tanh, speculative h_pre AND h =====
        tc = 0.0f; hp = 0.0f;
        if (tid < 160) {
            float iq = sh_act[tid], ff = sh_act[tid + 160], gg = sh_act[tid + 320];
            oq = sh_act[tid + 480];
            c_prev = c;
            c  = ff * c + iq * gg;
            tc = tanh_fast(c);
            hp = oq * fq1(tc, sc(k3p), scinv(k3p));
            float hq = fq1(hp, sc(khp), scinv(khp));            // speculative h
            sh_h[b * NH + g] = hq;
            out[((size_t)(bid * BPB + b) * T_STEPS + t) * NH + g] = hq;
        }
        if (wid < 5) {
            unsigned a1 = warp_max_u(__float_as_uint(fabsf(tc)));
            unsigned a2 = warp_max_u(__float_as_uint(fabsf(hp)));
            if (lane == 0) { atomicMax(&sh_red[8], a1); atomicMax(&sh_red[9], a2); }
        }
        if (sq >= 0 && t + 2 < T_STEPS)
            xr = x[((size_t)(bid * BPB + sxb) * T_STEPS + (t + 2)) * NI + sxi];
        __syncthreads();                                        // S2

        // ===== single grid barrier: gather, fire, poll, read, verify =====
        if (wid == 0) {
            unsigned v = (lane < 10) ? sh_red[lane] : 0u;
            __syncwarp();
            if (lane < 10) sh_red[lane] = 0u;
            unsigned n0 = __shfl_sync(0xffffffffu, v, 4);
            unsigned n1 = __shfl_sync(0xffffffffu, v, 5);
            unsigned n2 = __shfl_sync(0xffffffffu, v, 6);
            unsigned n3 = __shfl_sync(0xffffffffu, v, 7);
            unsigned t8 = __shfl_sync(0xffffffffu, v, 8);
            unsigned t9 = __shfl_sync(0xffffffffu, v, 9);
            unsigned myv = v;                                   // lanes 0-3: group max(pre)
            if (lane == 4) myv = n2;                            // max(-pre) tanh group
            if (lane == 5) myv = max(max(n0, n1), max(n2, n3)); // global max(-pre)
            if (lane == 6) myv = t8;                            // max|tanh c|
            if (lane == 7) myv = t9;                            // max|h_pre spec|
            if (lane < 8) red_max_rlx(cb + lane * CSTRIDE, myv);
            __syncwarp();
            nbar++;
            unsigned tgt = nbar * GB;
            if (lane == 0) red_add_rel(&g_ctr0[0], 1u);         // fire-and-forget
            if (lane < 8) { while (ld_acq(&g_ctr0[0]) < tgt) { } }
            __syncwarp();
            unsigned cv = (lane < 8) ? ld_rlx(cb + lane * CSTRIDE) : 0u;

            unsigned kk = (lane < 4 || lane == 5) ? cv : 0u;
            kk = max(kk, __shfl_xor_sync(0xffffffffu, kk, 4));
            kk = max(kk, __shfl_xor_sync(0xffffffffu, kk, 2));
            kk = max(kk, __shfl_xor_sync(0xffffffffu, kk, 1));
            int k1 = po2k(unmapf(kk));
            float s1 = sc(k1), v1 = scinv(k1);
            float mng = unmapf(__shfl_sync(0xffffffffu, cv, 4));
            float myp = unmapf(cv);
            float a;
            if (lane == 2) {
                float q1 = fq1(myp, s1, v1), q2 = fq1(-mng, s1, v1);
                a = tanh_fast(fmaxf(q1, -q2));
            } else {
                a = sigm(fq1(myp, s1, v1));
            }
            int ka  = po2k(fabsf(a));
            int k3t = po2k(__uint_as_float(__shfl_sync(0xffffffffu, cv, 6)));
            int kht = po2k(__uint_as_float(__shfl_sync(0xffffffffu, cv, 7)));
            bool okl = (lane < 4) ? (ka == sh_kp[1 + lane]) : true;
            unsigned bm = __ballot_sync(0xffffffffu, okl);
            int hit1 = (((bm & 0xFu) == 0xFu) && (k1 == sh_kp[0])) ? 1 : 0;
            int hit3 = (k3t == sh_kp[5]) ? 1 : 0;
            int hith = (kht == sh_kp[6]) ? 1 : 0;
            int code = hit1 ? (hit3 ? (hith ? 0 : 1) : 2) : 3;
            if (lane < 4) { sh_k[1 + lane] = ka; sh_kp[1 + lane] = ka; }
            if (lane == 0) {
                sh_k[0] = k1; sh_kp[0] = k1;
                if (hit1) { sh_k[5] = k3t; sh_kp[5] = k3t; }
                if (hit1 && hit3) { sh_k[6] = kht; sh_kp[6] = kht; }
                sh_k[7] = code;
            }
        }
        __syncthreads();                                        // S3

        const int code = sh_k[7];
        if (code == 0) continue;                                // full hit: done

        if (code == 1) {
            // kh miss only (cell 7 exact): local rewrite
            if (tid < 160) {
                float sh_ = sc(sh_k[6]), vh_ = scinv(sh_k[6]);
                float hq = fq1(hp, sh_, vh_);
                sh_h[b * NH + g] = hq;
                out[((size_t)(bid * BPB + b) * T_STEPS + t) * NH + g] = hq;
            }
            __syncthreads();
        } else if (code == 2) {
            // k3 miss (tc exact): recompute hp with true k3, one round for kh
            float s3 = sc(sh_k[5]), v3 = scinv(sh_k[5]);
            if (tid < 160) hp = oq * fq1(tc, s3, v3);
            if (wid < 5) {
                unsigned a2 = warp_max_u(__float_as_uint(fabsf(hp)));
                if (lane == 0) atomicMax(&sh_red[10], a2);
            }
            __syncthreads();
            if (wid == 0) {
                unsigned v = (lane == 0) ? sh_red[10] : 0u;
                __syncwarp();
                if (lane == 0) sh_red[10] = 0u;
                nbar++;
                unsigned cv = grid_bar(cb + 8 * CSTRIDE, v, 1, nbar * GB, lane);
                if (lane == 0) { sh_k[6] = po2k(__uint_as_float(cv)); sh_kp[6] = sh_k[6]; }
            }
            __syncthreads();
            if (tid < 160) {
                float sh_ = sc(sh_k[6]), vh_ = scinv(sh_k[6]);
                float hq = fq1(hp, sh_, vh_);
                sh_h[b * NH + g] = hq;
                out[((size_t)(bid * BPB + b) * T_STEPS + t) * NH + g] = hq;
            }
            __syncthreads();
        } else {
            // full miss: replay from exact pre / c_prev with true k1/ka
            {
                int k1 = sh_k[0], kat = sh_k[1 + gr];
                float gq  = fq1(pre, sc(k1), scinv(k1));
                float act = (gr == 2) ? tanh_fast(gq) : sigm(gq);
                sh_act[tid] = fq1(act, sc(kat), scinv(kat));
            }
            __syncthreads();
            int k3g = sh_kp[5];
            if (tid < 160) {
                float iq = sh_act[tid], ff = sh_act[tid + 160], gg = sh_act[tid + 320];
                oq = sh_act[tid + 480];
                c  = ff * c_prev + iq * gg;
                tc = tanh_fast(c);
                hp = oq * fq1(tc, sc(k3g), scinv(k3g));
            }
            if (wid < 5) {
                unsigned a1 = warp_max_u(__float_as_uint(fabsf(tc)));
                unsigned a2 = warp_max_u(__float_as_uint(fabsf(hp)));
                if (lane == 0) { atomicMax(&sh_red[10], a1); atomicMax(&sh_red[11], a2); }
            }
            __syncthreads();
            if (wid == 0) {
                unsigned v = (lane < 2) ? sh_red[10 + lane] : 0u;
                __syncwarp();
                if (lane < 2) sh_red[10 + lane] = 0u;
                nbar++;
                unsigned cv = grid_bar(cb + 9 * CSTRIDE, v, 2, nbar * GB, lane);
                int kx = po2k(__uint_as_float(cv));
                int k3 = __shfl_sync(0xffffffffu, kx, 0);
                int kh = __shfl_sync(0xffffffffu, kx, 1);
                if (lane == 0) {
                    sh_k[5] = k3; sh_kp[5] = k3; sh_k[6] = kh; sh_kp[6] = kh;
                    sh_k[7] = (k3 == k3g) ? 0 : 1;   // retry flag
                }
            }
            __syncthreads();
            if (sh_k[7]) {                           // k3 guess also missed
                float s3 = sc(sh_k[5]), v3 = scinv(sh_k[5]);
                if (tid < 160) hp = oq * fq1(tc, s3, v3);
                if (wid < 5) {
                    unsigned a2 = warp_max_u(__float_as_uint(fabsf(hp)));
                    if (lane == 0) atomicMax(&sh_red[10], a2);
                }
                __syncthreads();
                if (wid == 0) {
                    unsigned v = (lane == 0) ? sh_red[10] : 0u;
                    __syncwarp();
                    if (lane == 0) sh_red[10] = 0u;
                    nbar++;
                    unsigned cv = grid_bar(cb + 11 * CSTRIDE, v, 1, nbar * GB, lane);
                    if (lane == 0) { sh_k[6] = po2k(__uint_as_float(cv)); sh_kp[6] = sh_k[6]; }
                }
                __syncthreads();
            }
            if (tid < 160) {
                float sh_ = sc(sh_k[6]), vh_ = scinv(sh_k[6]);
                float hq = fq1(hp, sh_, vh_);
                sh_h[b * NH + g] = hq;
                out[((size_t)(bid * BPB + b) * T_STEPS + t) * NH + g] = hq;
            }
            __syncthreads();
        }
    }
}

extern "C" void kernel_launch(void* const* d_in, const int* in_sizes, int n_in,
                              void* d_out, int out_size) {
    (void)in_sizes; (void)n_in; (void)out_size;
    qlstm_init<<<32, 512>>>();
    qlstm_main<<<GB, NT>>>((const float*)d_in[0],
                           (const float*)d_in[1],
                           (const float*)d_in[2],
                           (float*)d_out);
}

// round 15
// speedup vs baseline: 1.0816x; 1.0816x over previous
#include <cuda_runtime.h>

// ---------------------------------------------------------------------------
// Quantized LSTM — R6 verbatim (single synchronous speculative grid barrier,
// red.max cells + acq_rel counter, post-barrier h-write with true kh, tiered
// fixups, exact tanhf/expf) with ONE change:
//   DEDICATED BARRIER WARP + EARLY FIRE.
//   phase C moves to warps 5-9; warp 0 gathers gate extrema and fires cells
//   0-5 immediately after S1 (overlapping phase C), then bar.sync(1,192)
//   with warps 5-9 replaces S2, then fires cells 6-7 + counter.
// ---------------------------------------------------------------------------

#define GB       128
#define BPB      8
#define NT       640
#define T_STEPS  1024
#define NI       10
#define NH       20
#define NG       80
#define CSTRIDE  64              // 256B between cells
#define NCELL    16              // 0-7 main, 8 c1-fix, 9-10 c2-fix, 11 retry

__device__ __align__(128) unsigned g_ctr0[32];
__device__ unsigned g_cells[T_STEPS * NCELL * CSTRIDE];

__global__ void qlstm_init() {
    int i = blockIdx.x * blockDim.x + threadIdx.x;   // 16384 = T_STEPS*NCELL
    if (i == 0) g_ctr0[0] = 0u;
    if (i < T_STEPS * NCELL) g_cells[i * CSTRIDE] = 0u;
}

__device__ __forceinline__ unsigned mapf(float f) {
    unsigned u = __float_as_uint(f);
    return (u & 0x80000000u) ? ~u : (u | 0x80000000u);
}
__device__ __forceinline__ float unmapf(unsigned u) {
    return __uint_as_float((u & 0x80000000u) ? (u & 0x7FFFFFFFu) : ~u);
}
__device__ __forceinline__ int po2k(float m) {
    m = fmaxf(m, 1e-8f);
    int e; float f = frexpf(m, &e);
    return (f == 0.5f) ? (e - 1) : e;
}
__device__ __forceinline__ float sc(int k)    { return __uint_as_float((unsigned)(k + 120) << 23); }
__device__ __forceinline__ float scinv(int k) { return __uint_as_float((unsigned)(134 - k) << 23); }
__device__ __forceinline__ float fq1(float x, float s, float inv) {
    float q = rintf(x * inv);
    q = fminf(fmaxf(q, -128.0f), 127.0f);
    return q * s;
}
__device__ __forceinline__ float sigm(float x) { return 1.0f / (1.0f + expf(-x)); }
__device__ __forceinline__ unsigned warp_max_u(unsigned v) {
#pragma unroll
    for (int o = 16; o; o >>= 1) v = max(v, __shfl_xor_sync(0xffffffffu, v, o));
    return v;
}
__device__ __forceinline__ void red_max_rlx(unsigned* p, unsigned v) {
    asm volatile("red.relaxed.gpu.max.u32 [%0],%1;" :: "l"(p), "r"(v) : "memory");
}
__device__ __forceinline__ unsigned atom_add_acqrel(unsigned* p, unsigned v) {
    unsigned old;
    asm volatile("atom.acq_rel.gpu.add.u32 %0,[%1],%2;" : "=r"(old) : "l"(p), "r"(v) : "memory");
    return old;
}
__device__ __forceinline__ unsigned ld_acq(const unsigned* p) {
    unsigned v; asm volatile("ld.acquire.gpu.u32 %0,[%1];" : "=r"(v) : "l"(p) : "memory"); return v;
}
__device__ __forceinline__ unsigned ld_rlx(const unsigned* p) {
    unsigned v; asm volatile("ld.relaxed.gpu.u32 %0,[%1];" : "=r"(v) : "l"(p) : "memory"); return v;
}

// fallback grid round (rare path), R6 protocol
__device__ __forceinline__ unsigned grid_bar(unsigned* cell0, unsigned myv, int nc,
                                             unsigned tgt, int lane) {
    if (lane < nc) red_max_rlx(cell0 + lane * CSTRIDE, myv);
    __syncwarp();
    unsigned last = 0;
    if (lane == 0) last = (atom_add_acqrel(&g_ctr0[0], 1u) == tgt - 1u) ? 1u : 0u;
    last = __shfl_sync(0xffffffffu, last, 0);
    if (!last) { while (ld_acq(&g_ctr0[0]) < tgt) { } }
    __syncwarp();
    return (lane < nc) ? ld_rlx(cell0 + lane * CSTRIDE) : 0u;
}

__global__ void __launch_bounds__(NT, 1) qlstm_main(
    const float* __restrict__ x,
    const float* __restrict__ Wih,
    const float* __restrict__ Whh,
    float* __restrict__ out)
{
    __shared__ __align__(16) float sh_h[BPB * NH];
    __shared__ __align__(16) float sh_x[BPB * NI];
    __shared__ float               sh_act[NG * BPB];
    __shared__ unsigned            sh_red[12];
    __shared__ int                 sh_k[8];    // 0:k1 1-4:ka 5:k3 6:kh 7:code
    __shared__ int                 sh_kp[6];   // predictions: k1, ka0-3, k3

    const int tid  = threadIdx.x;
    const int bid  = blockIdx.x;
    const int g    = tid / BPB;
    const int b    = tid % BPB;
    const int gr   = tid / 160;          // warp-uniform gate group
    const int lane = tid & 31;
    const int wid  = tid >> 5;
    const bool isC = (wid >= 5 && wid < 10);   // phase-C warps (tid 160-319)
    const int  loc = tid - 160;                // 0..159 when isC
    const int  cj  = loc / BPB;                // hidden index
    const int  cb  = loc % BPB;                // batch

    if (tid < 12) sh_red[tid] = 0u;
    if (tid < 6)  sh_kp[tid] = 99;       // garbage -> full miss at t=0
    if (tid < 8)  sh_k[tid] = 0;
    if (tid < BPB * NH) sh_h[tid] = 0.0f;
    __syncthreads();

    // ---- weight scale (block-local, once) ----
    {
        float wm = 0.0f;
        for (int k = tid; k < NG * NI; k += NT) wm = fmaxf(wm, fabsf(Wih[k]));
        for (int k = tid; k < NG * NH; k += NT) wm = fmaxf(wm, fabsf(Whh[k]));
        unsigned u = warp_max_u(__float_as_uint(wm));
        if (lane == 0) atomicMax(&sh_red[11], u);
        __syncthreads();
    }
    int kw = po2k(__uint_as_float(sh_red[11]));
    float ws = sc(kw), wsi = scinv(kw);
    __syncthreads();
    if (tid == 0) sh_red[11] = 0u;
    __syncthreads();

    float wi[NI], wh[NH];
#pragma unroll
    for (int i2 = 0; i2 < NI; i2++) wi[i2] = fq1(Wih[g * NI + i2], ws, wsi);
#pragma unroll
    for (int j2 = 0; j2 < NH; j2++) wh[j2] = fq1(Whh[g * NH + j2], ws, wsi);

    float    c = 0.0f, c_prev = 0.0f;    // phase-C state (isC threads)
    float    tc = 0.0f, oq = 0.0f, hp = 0.0f;
    unsigned nbar = 0;

    const int sq  = tid - 560;           // warps 17-19 stage x
    const int sxb = (sq >= 0) ? sq / NI : 0;
    const int sxi = (sq >= 0) ? sq % NI : 0;
    float xr = 0.0f;
    if (sq >= 0) {
        sh_x[sq] = x[((size_t)(bid * BPB + sxb) * T_STEPS + 0) * NI + sxi];
        xr       = x[((size_t)(bid * BPB + sxb) * T_STEPS + 1) * NI + sxi];
    }
    __syncthreads();

    for (int t = 0; t < T_STEPS; ++t) {
        const int k1p = sh_kp[0], kap = sh_kp[1 + gr], k3p = sh_kp[5];
        unsigned* cb_ = &g_cells[(size_t)t * NCELL * CSTRIDE];

        // ===== phase B (all warps): pre + gate extrema + speculative act =====
        float p0 = 0.0f, p1 = 0.0f;
        {
            const float2* px = reinterpret_cast<const float2*>(&sh_x[b * NI]);
            const float2* ph = reinterpret_cast<const float2*>(&sh_h[b * NH]);
#pragma unroll
            for (int j = 0; j < NI / 2; j++) {
                float2 v = px[j];
                p0 = fmaf(v.x, wi[2 * j], p0); p1 = fmaf(v.y, wi[2 * j + 1], p1);
            }
#pragma unroll
            for (int j = 0; j < NH / 2; j++) {
                float2 v = ph[j];
                p0 = fmaf(v.x, wh[2 * j], p0); p1 = fmaf(v.y, wh[2 * j + 1], p1);
            }
        }
        float pre = p0 + p1;
        unsigned kp = warp_max_u(mapf(pre));
        unsigned kn = warp_max_u(mapf(-pre));
        if (lane == 0) { atomicMax(&sh_red[gr], kp); atomicMax(&sh_red[4 + gr], kn); }
        {
            float gq  = fq1(pre, sc(k1p), scinv(k1p));
            float act = (gr == 2) ? tanhf(gq) : sigm(gq);
            sh_act[tid] = fq1(act, sc(kap), scinv(kap));
        }
        __syncthreads();                                        // S1

        if (wid == 0) {
            // ---- dedicated barrier warp: gather + EARLY FIRE cells 0-5 ----
            unsigned v = (lane < 8) ? sh_red[lane] : 0u;
            __syncwarp();
            if (lane < 8) sh_red[lane] = 0u;
            unsigned n0 = __shfl_sync(0xffffffffu, v, 4);
            unsigned n1 = __shfl_sync(0xffffffffu, v, 5);
            unsigned n2 = __shfl_sync(0xffffffffu, v, 6);
            unsigned n3 = __shfl_sync(0xffffffffu, v, 7);
            unsigned myv = v;
            if (lane == 4) myv = n2;                            // max(-pre) tanh group
            if (lane == 5) myv = max(max(n0, n1), max(n2, n3)); // global max(-pre)
            if (lane < 6) red_max_rlx(cb_ + lane * CSTRIDE, myv);
        } else if (isC) {
            // ---- phase C (warps 5-9): c update, tanh, speculative h_pre ----
            float iq = sh_act[loc], ff = sh_act[loc + 160];
            float gg = sh_act[loc + 320]; oq = sh_act[loc + 480];
            c_prev = c;
            c  = ff * c + iq * gg;
            tc = tanhf(c);
            hp = oq * fq1(tc, sc(k3p), scinv(k3p));
            unsigned a1 = warp_max_u(__float_as_uint(fabsf(tc)));
            unsigned a2 = warp_max_u(__float_as_uint(fabsf(hp)));
            if (lane == 0) { atomicMax(&sh_red[8], a1); atomicMax(&sh_red[9], a2); }
        } else if (sq >= 0) {
            if (t + 1 < T_STEPS) sh_x[sq] = xr;                 // publish x(t+1)
            if (t + 2 < T_STEPS)
                xr = x[((size_t)(bid * BPB + sxb) * T_STEPS + (t + 2)) * NI + sxi];
        }

        if (wid == 0 || isC)
            asm volatile("bar.sync 1, 192;" ::: "memory");      // {w0, w5-9}

        // ===== warp 0: fire cells 6-7 + counter, poll, read, verify =====
        if (wid == 0) {
            unsigned v89 = (lane < 2) ? sh_red[8 + lane] : 0u;
            __syncwarp();
            if (lane < 2) sh_red[8 + lane] = 0u;
            unsigned t8 = __shfl_sync(0xffffffffu, v89, 0);
            unsigned t9 = __shfl_sync(0xffffffffu, v89, 1);
            if (lane == 6) red_max_rlx(cb_ + 6 * CSTRIDE, t8);
            if (lane == 7) red_max_rlx(cb_ + 7 * CSTRIDE, t9);
            __syncwarp();
            nbar++;
            unsigned tgt = nbar * GB, last = 0;
            if (lane == 0) last = (atom_add_acqrel(&g_ctr0[0], 1u) == tgt - 1u) ? 1u : 0u;
            last = __shfl_sync(0xffffffffu, last, 0);
            if (!last) { while (ld_acq(&g_ctr0[0]) < tgt) { } }
            __syncwarp();
            unsigned cv = (lane < 8) ? ld_rlx(cb_ + lane * CSTRIDE) : 0u;

            unsigned kk = (lane < 4 || lane == 5) ? cv : 0u;
            kk = max(kk, __shfl_xor_sync(0xffffffffu, kk, 4));
            kk = max(kk, __shfl_xor_sync(0xffffffffu, kk, 2));
            kk = max(kk, __shfl_xor_sync(0xffffffffu, kk, 1));
            int k1 = po2k(unmapf(kk));
            float s1 = sc(k1), v1 = scinv(k1);
            float mng = unmapf(__shfl_sync(0xffffffffu, cv, 4));
            float myp = unmapf(cv);
            float a;
            if (lane == 2) {
                float q1 = fq1(myp, s1, v1), q2 = fq1(-mng, s1, v1);
                a = tanhf(fmaxf(q1, -q2));
            } else {
                a = sigm(fq1(myp, s1, v1));
            }
            int ka  = po2k(fabsf(a));
            int k3t = po2k(__uint_as_float(__shfl_sync(0xffffffffu, cv, 6)));
            int kht = po2k(__uint_as_float(__shfl_sync(0xffffffffu, cv, 7)));
            bool okl = (lane < 4) ? (ka == sh_kp[1 + lane]) : true;
            unsigned bm = __ballot_sync(0xffffffffu, okl);
            int hit1 = (((bm & 0xFu) == 0xFu) && (k1 == sh_kp[0])) ? 1 : 0;
            int hit3 = (k3t == sh_kp[5]) ? 1 : 0;
            int code = hit1 ? (hit3 ? 0 : 1) : 2;
            if (lane < 4) { sh_k[1 + lane] = ka; sh_kp[1 + lane] = ka; }
            if (lane == 0) {
                sh_k[0] = k1; sh_kp[0] = k1;
                if (hit1) { sh_k[5] = k3t; sh_kp[5] = k3t; }
                if (hit1 && hit3) sh_k[6] = kht;     // cell7 exact only when hit1&hit3
                sh_k[7] = code;
            }
        }
        __syncthreads();                                        // S3

        const int code = sh_k[7];
        if (code == 1) {
            // k3 miss (tc exact): recompute hp with true k3, one round for kh
            if (isC) {
                float s3 = sc(sh_k[5]), v3 = scinv(sh_k[5]);
                hp = oq * fq1(tc, s3, v3);
                unsigned a2 = warp_max_u(__float_as_uint(fabsf(hp)));
                if (lane == 0) atomicMax(&sh_red[10], a2);
            }
            __syncthreads();
            if (wid == 0) {
                unsigned v = (lane == 0) ? sh_red[10] : 0u;
                __syncwarp();
                if (lane == 0) sh_red[10] = 0u;
                nbar++;
                unsigned cv = grid_bar(cb_ + 8 * CSTRIDE, v, 1, nbar * GB, lane);
                if (lane == 0) sh_k[6] = po2k(__uint_as_float(cv));
            }
            __syncthreads();
        } else if (code == 2) {
            // full miss: replay from exact pre / c_prev with true k1/ka
            {
                int k1 = sh_k[0], kat = sh_k[1 + gr];
                float gq  = fq1(pre, sc(k1), scinv(k1));
                float act = (gr == 2) ? tanhf(gq) : sigm(gq);
                sh_act[tid] = fq1(act, sc(kat), scinv(kat));
            }
            __syncthreads();
            int k3g = sh_kp[5];
            if (isC) {
                float iq = sh_act[loc], ff = sh_act[loc + 160];
                float gg = sh_act[loc + 320]; oq = sh_act[loc + 480];
                c  = ff * c_prev + iq * gg;
                tc = tanhf(c);
                hp = oq * fq1(tc, sc(k3g), scinv(k3g));
                unsigned a1 = warp_max_u(__float_as_uint(fabsf(tc)));
                unsigned a2 = warp_max_u(__float_as_uint(fabsf(hp)));
                if (lane == 0) { atomicMax(&sh_red[10], a1); atomicMax(&sh_red[11], a2); }
            }
            __syncthreads();
            if (wid == 0) {
                unsigned v = (lane < 2) ? sh_red[10 + lane] : 0u;
                __syncwarp();
                if (lane < 2) sh_red[10 + lane] = 0u;
                nbar++;
                unsigned cv = grid_bar(cb_ + 9 * CSTRIDE, v, 2, nbar * GB, lane);
                int kx = po2k(__uint_as_float(cv));
                int k3 = __shfl_sync(0xffffffffu, kx, 0);
                int kh = __shfl_sync(0xffffffffu, kx, 1);
                if (lane == 0) {
                    sh_k[5] = k3; sh_kp[5] = k3; sh_k[6] = kh;
                    sh_k[7] = (k3 == k3g) ? 0 : 1;   // retry flag
                }
            }
            __syncthreads();
            if (sh_k[7]) {                           // k3 guess also missed
                if (isC) {
                    float s3 = sc(sh_k[5]), v3 = scinv(sh_k[5]);
                    hp = oq * fq1(tc, s3, v3);
                    unsigned a2 = warp_max_u(__float_as_uint(fabsf(hp)));
                    if (lane == 0) atomicMax(&sh_red[10], a2);
                }
                __syncthreads();
                if (wid == 0) {
                    unsigned v = (lane == 0) ? sh_red[10] : 0u;
                    __syncwarp();
                    if (lane == 0) sh_red[10] = 0u;
                    nbar++;
                    unsigned cv = grid_bar(cb_ + 11 * CSTRIDE, v, 1, nbar * GB, lane);
                    if (lane == 0) sh_k[6] = po2k(__uint_as_float(cv));
                }
                __syncthreads();
            }
        }

        // ===== h quantize with true kh, publish, output (R6 hit path) =====
        if (isC) {
            int kh = sh_k[6];
            float hq = fq1(hp, sc(kh), scinv(kh));
            sh_h[cb * NH + cj] = hq;
            out[((size_t)(bid * BPB + cb) * T_STEPS + t) * NH + cj] = hq;
        }
        __syncthreads();                                        // S4
    }
}

extern "C" void kernel_launch(void* const* d_in, const int* in_sizes, int n_in,
                              void* d_out, int out_size) {
    (void)in_sizes; (void)n_in; (void)out_size;
    qlstm_init<<<32, 512>>>();
    qlstm_main<<<GB, NT>>>((const float*)d_in[0],
                           (const float*)d_in[1],
                           (const float*)d_in[2],
                           (float*)d_out);
}